// round 4
// baseline (speedup 1.0000x reference)
#include <cuda_runtime.h>
#include <math_constants.h>

#define BB    32
#define NN    512
#define DIN_  768
#define DOUT_ 256
#define MROWS (BB * NN)          // 16384
#define NEGV  (-9.0e15f)
#define SLOPE 0.2f

// Scratch (device globals: allocation-free)
__device__ float g_Wh[MROWS * DOUT_];   // 16 MB
__device__ float g_s1[MROWS];
__device__ float g_s2[MROWS];

// ---------------------------------------------------------------------------
// Kernel 1: Wh = h @ W + pos_table[positions]
// M=16384, K=768, N=256. Block tile 64x64, BK=16, 256 threads, 4x4 per thread.
// ---------------------------------------------------------------------------
__global__ void gemm_wh_kernel(const float* __restrict__ h,
                               const float* __restrict__ W,
                               const int*   __restrict__ positions,
                               const float* __restrict__ pos_table) {
    __shared__ float As[16][68];   // [k][m], padded (68*4=272B, 16B aligned rows)
    __shared__ float Bs[16][64];   // [k][n]

    const int tid = threadIdx.x;
    const int m0 = blockIdx.y * 64;
    const int n0 = blockIdx.x * 64;

    const int arow  = tid >> 2;    // 0..63
    const int acol4 = tid & 3;     // 0..3  (4 float4 per A row of 16)
    const int brow  = tid >> 4;    // 0..15
    const int bf4   = tid & 15;    // 0..15
    const int tx    = tid & 15;    // n-direction
    const int ty    = tid >> 4;    // m-direction

    float acc[4][4];
#pragma unroll
    for (int i = 0; i < 4; i++)
#pragma unroll
        for (int j = 0; j < 4; j++) acc[i][j] = 0.f;

    const float* hA = &h[(size_t)(m0 + arow) * DIN_];

    for (int k0 = 0; k0 < DIN_; k0 += 16) {
        float4 av = *(const float4*)&hA[k0 + acol4 * 4];
        float4 bv = *(const float4*)&W[(size_t)(k0 + brow) * DOUT_ + n0 + bf4 * 4];
        __syncthreads();
        As[acol4 * 4 + 0][arow] = av.x;
        As[acol4 * 4 + 1][arow] = av.y;
        As[acol4 * 4 + 2][arow] = av.z;
        As[acol4 * 4 + 3][arow] = av.w;
        *(float4*)&Bs[brow][bf4 * 4] = bv;
        __syncthreads();
#pragma unroll
        for (int k = 0; k < 16; k++) {
            float4 a = *(float4*)&As[k][ty * 4];
            float4 b = *(float4*)&Bs[k][tx * 4];
            float ar[4] = {a.x, a.y, a.z, a.w};
            float br[4] = {b.x, b.y, b.z, b.w};
#pragma unroll
            for (int i = 0; i < 4; i++)
#pragma unroll
                for (int j = 0; j < 4; j++) acc[i][j] = fmaf(ar[i], br[j], acc[i][j]);
        }
    }

#pragma unroll
    for (int i = 0; i < 4; i++) {
        int row = m0 + ty * 4 + i;
        int pos = positions[row];
        const float4 pt = *(const float4*)&pos_table[(size_t)pos * DOUT_ + n0 + tx * 4];
        float4 o;
        o.x = acc[i][0] + pt.x;
        o.y = acc[i][1] + pt.y;
        o.z = acc[i][2] + pt.z;
        o.w = acc[i][3] + pt.w;
        *(float4*)&g_Wh[(size_t)row * DOUT_ + n0 + tx * 4] = o;
    }
}

// ---------------------------------------------------------------------------
// Kernel 2: s1 = Wh . a1, s2 = Wh . a2 per row. One warp per row.
// ---------------------------------------------------------------------------
__global__ void s12_kernel(const float* __restrict__ a1,
                           const float* __restrict__ a2) {
    __shared__ float sa1[DOUT_], sa2[DOUT_];
    const int tid = threadIdx.x;
    sa1[tid] = a1[tid];
    sa2[tid] = a2[tid];
    __syncthreads();

    const int warp = tid >> 5, lane = tid & 31;
    const int row = blockIdx.x * 8 + warp;
    const float* wr = &g_Wh[(size_t)row * DOUT_];

    float p1 = 0.f, p2 = 0.f;
#pragma unroll
    for (int c = 0; c < 2; c++) {
        int idx = (c * 32 + lane) * 4;
        float4 v = *(const float4*)&wr[idx];
        p1 += v.x * sa1[idx] + v.y * sa1[idx + 1] + v.z * sa1[idx + 2] + v.w * sa1[idx + 3];
        p2 += v.x * sa2[idx] + v.y * sa2[idx + 1] + v.z * sa2[idx + 2] + v.w * sa2[idx + 3];
    }
#pragma unroll
    for (int o = 16; o; o >>= 1) {
        p1 += __shfl_xor_sync(0xFFFFFFFFu, p1, o);
        p2 += __shfl_xor_sync(0xFFFFFFFFu, p2, o);
    }
    if (lane == 0) {
        g_s1[row] = p1;
        g_s2[row] = p2;
    }
}

// ---------------------------------------------------------------------------
// Kernel 3: masked softmax attention + h_prime = att @ Wh.
// One block per (batch b, tile of 32 i-rows). 256 threads.
// Dynamic smem: att[32][512] (64KB) + s2[512] (2KB).
// ---------------------------------------------------------------------------
extern __shared__ float smem3[];

__global__ void attn_kernel(const int* __restrict__ adj,
                            float* __restrict__ out_h,
                            float* __restrict__ out_att) {
    float* s_att = smem3;              // 32 * 512
    float* s_s2  = smem3 + 32 * NN;    // 512

    const int tid = threadIdx.x;
    const int blk = blockIdx.x;
    const int b  = blk >> 4;           // 16 tiles per batch
    const int it = blk & 15;

    s_s2[tid]       = g_s2[b * NN + tid];
    s_s2[tid + 256] = g_s2[b * NN + tid + 256];
    __syncthreads();

    const int warp = tid >> 5, lane = tid & 31;

    // Phase A: per-row masked leaky-relu softmax; each warp does 4 rows.
    for (int r = 0; r < 4; r++) {
        const int li = warp * 4 + r;           // 0..31
        const int ii = it * 32 + li;
        const int grow = b * NN + ii;
        const float s1i = g_s1[grow];
        const int* arow = &adj[(size_t)grow * NN];
        float* att_row = &s_att[li * NN];

        float m = -CUDART_INF_F;
#pragma unroll
        for (int jj = 0; jj < 16; jj++) {
            int j = jj * 32 + lane;
            float e = s1i + s_s2[j];
            e = e > 0.f ? e : SLOPE * e;
            float v = (arow[j] > 0) ? e : NEGV;
            att_row[j] = v;
            m = fmaxf(m, v);
        }
#pragma unroll
        for (int o = 16; o; o >>= 1) m = fmaxf(m, __shfl_xor_sync(0xFFFFFFFFu, m, o));

        float s = 0.f;
#pragma unroll
        for (int jj = 0; jj < 16; jj++) {
            int j = jj * 32 + lane;
            float p = __expf(att_row[j] - m);
            att_row[j] = p;
            s += p;
        }
#pragma unroll
        for (int o = 16; o; o >>= 1) s += __shfl_xor_sync(0xFFFFFFFFu, s, o);
        const float rinv = 1.f / s;

        float* gatt = &out_att[(size_t)grow * NN];
#pragma unroll
        for (int jj = 0; jj < 16; jj++) {
            int j = jj * 32 + lane;
            float p = att_row[j] * rinv;
            att_row[j] = p;
            gatt[j] = p;
        }
    }
    __syncthreads();

    // Phase B: h_prime tile [32 x 256] = att [32 x 512] @ Wh_b [512 x 256].
    // Thread t owns output dim d = t for all 32 rows.
    const int d = tid;
    float acc[32];
#pragma unroll
    for (int i = 0; i < 32; i++) acc[i] = 0.f;

    const float* whb = &g_Wh[(size_t)b * NN * DOUT_ + d];
    for (int j4 = 0; j4 < NN / 4; j4++) {
        float w0 = whb[(size_t)(j4 * 4 + 0) * DOUT_];
        float w1 = whb[(size_t)(j4 * 4 + 1) * DOUT_];
        float w2 = whb[(size_t)(j4 * 4 + 2) * DOUT_];
        float w3 = whb[(size_t)(j4 * 4 + 3) * DOUT_];
#pragma unroll
        for (int i = 0; i < 32; i++) {
            float4 a = *(float4*)&s_att[i * NN + j4 * 4];
            acc[i] = fmaf(a.x, w0, acc[i]);
            acc[i] = fmaf(a.y, w1, acc[i]);
            acc[i] = fmaf(a.z, w2, acc[i]);
            acc[i] = fmaf(a.w, w3, acc[i]);
        }
    }

    const int ibase = it * 32;
#pragma unroll
    for (int i = 0; i < 32; i++)
        out_h[(size_t)(b * NN + ibase + i) * DOUT_ + d] = acc[i];
}

// ---------------------------------------------------------------------------
extern "C" void kernel_launch(void* const* d_in, const int* in_sizes, int n_in,
                              void* d_out, int out_size) {
    const float* h         = (const float*)d_in[0];
    const int*   adj       = (const int*)  d_in[1];
    const int*   positions = (const int*)  d_in[2];
    const float* W         = (const float*)d_in[3];
    const float* a1        = (const float*)d_in[4];
    const float* a2        = (const float*)d_in[5];
    const float* pos_table = (const float*)d_in[6];

    float* out_h   = (float*)d_out;                          // [32,512,256]
    float* out_att = (float*)d_out + (size_t)BB * NN * DOUT_; // [32,512,512]

    dim3 g1(DOUT_ / 64, MROWS / 64);
    gemm_wh_kernel<<<g1, 256>>>(h, W, positions, pos_table);

    s12_kernel<<<MROWS / 8, 256>>>(a1, a2);

    const int smem3_sz = (32 * NN + NN) * (int)sizeof(float);  // 67584 B
    cudaFuncSetAttribute(attn_kernel, cudaFuncAttributeMaxDynamicSharedMemorySize,
                         smem3_sz);
    attn_kernel<<<BB * 16, 256, smem3_sz>>>(adj, out_h, out_att);
}